// round 15
// baseline (speedup 1.0000x reference)
#include <cuda_runtime.h>
#include <cuda_fp16.h>
#include <math.h>

// Problem-fixed sizes: N=50000, E=1600000, C=64, K=5 (25 kernels)
#define MAXN 50176
#define MAXE 1600000
#define C 64
#define KK 25
#define SCAN_B 1024

// Scratch. xk layout: [n][k][64] fp16 (single buffer).
static __device__ __half g_xk[(size_t)MAXN * KK * C];    // 160MB
static __device__ float  g_h[(size_t)MAXN * C];
static __device__ float  g_rootout[(size_t)MAXN * C];
static __device__ float  g_aggbuf[(size_t)MAXN * C];
static __device__ uint2  g_wf1[26 * 4 * 8 * 32];
static __device__ uint2  g_wf2[26 * 4 * 8 * 32];
static __device__ int    g_deg[2 * MAXN];
static __device__ int    g_cursor[2 * MAXN];
static __device__ int    g_off[2 * MAXN];
static __device__ int    g_offp[2 * MAXN];
static __device__ int    g_bsum[128];
static __device__ uint2  g_emeta[MAXE];

// ---------------------------------------------------------------------------
__device__ __forceinline__ void mma_f16(float* c,
                                        unsigned a0, unsigned a1, unsigned a2, unsigned a3,
                                        unsigned b0, unsigned b1) {
    asm("mma.sync.aligned.m16n8k16.row.col.f32.f16.f16.f32 "
        "{%0,%1,%2,%3}, {%4,%5,%6,%7}, {%8,%9}, {%0,%1,%2,%3};"
        : "+f"(c[0]), "+f"(c[1]), "+f"(c[2]), "+f"(c[3])
        : "r"(a0), "r"(a1), "r"(a2), "r"(a3), "r"(b0), "r"(b1));
}

// ---------------------------------------------------------------------------
__global__ void cvt_w_kernel(const float* __restrict__ W, const float* __restrict__ root,
                             uint2* __restrict__ frag) {
    int idx = blockIdx.x * blockDim.x + threadIdx.x;
    if (idx >= 26 * 4 * 8 * 32) return;
    int lane = idx & 31;
    int nt   = (idx >> 5) & 7;
    int s    = (idx >> 8) & 3;
    int k    = idx >> 10;
    int gy = lane >> 2, gx = lane & 3;
    int o = nt * 8 + gy;
    int i = s * 16 + 2 * gx;
    const float* src = (k < KK) ? (W + (size_t)k * 4096) : root;
    __half2 b0 = __floats2half2_rn(src[i * 64 + o],       src[(i + 1) * 64 + o]);
    __half2 b1 = __floats2half2_rn(src[(i + 8) * 64 + o], src[(i + 9) * 64 + o]);
    frag[idx] = make_uint2(*(unsigned*)&b0, *(unsigned*)&b1);
}

// ---------------------------------------------------------------------------
// Edge bucketing by (pass, dst)
// ---------------------------------------------------------------------------
__device__ __forceinline__ int edge_pass(float u1) {
    float v1 = u1 * 4.0f;
    int i1 = (int)floorf(v1);
    int i1a = min(max(i1, 0), 4);
    return (i1a <= 1) ? 0 : 1;
}

__global__ void zero_kernel(int* __restrict__ deg, int* __restrict__ cur, int total) {
    int i = blockIdx.x * blockDim.x + threadIdx.x;
    if (i < total) { deg[i] = 0; cur[i] = 0; }
}

__global__ void hist_kernel(const int* __restrict__ dst, const float* __restrict__ pseudo,
                            int* __restrict__ deg, int E, int N) {
    int e = blockIdx.x * blockDim.x + threadIdx.x;
    if (e < E) {
        int p = edge_pass(pseudo[2 * e + 1]);
        atomicAdd(&deg[p * N + dst[e]], 1);
    }
}

__global__ void scan_local_kernel(const int* __restrict__ deg, int* __restrict__ offp,
                                  int* __restrict__ bsum, int total) {
    __shared__ int s[SCAN_B];
    int tid = threadIdx.x;
    int g = blockIdx.x * SCAN_B + tid;
    int v = (g < total) ? deg[g] : 0;
    s[tid] = v;
    __syncthreads();
#pragma unroll
    for (int o = 1; o < SCAN_B; o <<= 1) {
        int t = (tid >= o) ? s[tid - o] : 0;
        __syncthreads();
        s[tid] += t;
        __syncthreads();
    }
    if (g < total) offp[g] = s[tid] - v;
    if (tid == SCAN_B - 1) bsum[blockIdx.x] = s[tid];
}

__global__ void scan_bsum_kernel(int* __restrict__ bsum, int NB) {
    __shared__ int s[128];
    int tid = threadIdx.x;
    int v = (tid < NB) ? bsum[tid] : 0;
    s[tid] = v;
    __syncthreads();
#pragma unroll
    for (int o = 1; o < 128; o <<= 1) {
        int t = (tid >= o) ? s[tid - o] : 0;
        __syncthreads();
        s[tid] += t;
        __syncthreads();
    }
    if (tid < NB) bsum[tid] = s[tid] - v;
}

__global__ void scan_add_kernel(const int* __restrict__ offp, const int* __restrict__ bsum,
                                int* __restrict__ off, int total) {
    int i = blockIdx.x * blockDim.x + threadIdx.x;
    if (i < total) off[i] = offp[i] + bsum[i / SCAN_B];
}

__global__ void scatter_kernel(const int* __restrict__ src, const int* __restrict__ dst,
                               const float* __restrict__ pseudo,
                               const int* __restrict__ off, int* __restrict__ cur,
                               uint2* __restrict__ emeta, int E, int N) {
    int e = blockIdx.x * blockDim.x + threadIdx.x;
    if (e >= E) return;
    int d = dst[e];
    int s = src[e];
    float v0 = pseudo[2 * e + 0] * 4.0f;
    float v1 = pseudo[2 * e + 1] * 4.0f;
    float b0f = floorf(v0), b1f = floorf(v1);
    float f0 = v0 - b0f, f1 = v1 - b1f;
    int i0 = (int)b0f, i1 = (int)b1f;
    int i0a = min(max(i0, 0), 4);
    int i0b = min(max(i0 + 1, 0), 4);
    int i1a = min(max(i1, 0), 4);
    int i1b = min(max(i1 + 1, 0), 4);
    int p = (i1a <= 1) ? 0 : 1;

    unsigned w0 = (unsigned)s | ((unsigned)i0a << 17) | ((unsigned)i1a << 20)
                | ((unsigned)(i0b - i0a) << 23) | ((unsigned)(i1b - i1a) << 24);
    __half2 fh = __floats2half2_rn(f0, f1);
    unsigned w1 = *(unsigned*)&fh;

    int pos = off[p * N + d] + atomicAdd(&cur[p * N + d], 1);
    emeta[pos] = make_uint2(w0, w1);
}

// ---------------------------------------------------------------------------
// GEMM (fp16 MMA m16n8k16): 128-node tile (finer wave-quantization), 256
// threads = 8 warps x 16 rows each. 26 matrices. B frags from packed global
// (L1-resident); A frags register-resident across all 26 matrices.
// xk stores staged through smem -> coalesced 128B-row STG.128.
// ---------------------------------------------------------------------------
__global__ void __launch_bounds__(256, 4)
gemm_xk_kernel(const float* __restrict__ x,
               const uint2* __restrict__ Wf,
               const float* __restrict__ bias,
               __half* __restrict__ xk,
               float* __restrict__ rootout, int N) {
    __shared__ __half xs[128 * 72];     // x tile; later reused as store stage
    const int tid  = threadIdx.x;
    const int lane = tid & 31;
    const int warp = tid >> 5;
    const int n0   = blockIdx.x * 128;

    for (int t = tid; t < 128 * 16; t += 256) {
        int r = t >> 4, c = (t & 15) * 4;
        int n = n0 + r;
        float4 v = (n < N) ? *(const float4*)&x[(size_t)n * C + c]
                           : make_float4(0.f, 0.f, 0.f, 0.f);
        __half2* p = (__half2*)&xs[r * 72 + c];
        p[0] = __floats2half2_rn(v.x, v.y);
        p[1] = __floats2half2_rn(v.z, v.w);
    }
    __syncthreads();

    const int gy = lane >> 2;
    const int gx = lane & 3;
    const int m0 = warp * 16;           // one m16 tile per warp

    unsigned A[4][4];
#pragma unroll
    for (int s = 0; s < 4; ++s) {
        int k0 = s * 16;
        A[s][0] = *(const unsigned*)&xs[(m0 + gy)     * 72 + k0 + 2 * gx];
        A[s][1] = *(const unsigned*)&xs[(m0 + gy + 8) * 72 + k0 + 2 * gx];
        A[s][2] = *(const unsigned*)&xs[(m0 + gy)     * 72 + k0 + 2 * gx + 8];
        A[s][3] = *(const unsigned*)&xs[(m0 + gy + 8) * 72 + k0 + 2 * gx + 8];
    }
    __syncthreads();   // x tile fully consumed; xs becomes per-warp store stage

    __half* stage = &xs[warp * 16 * 72];    // 16 rows x 72 halves per warp
    const int srow = lane >> 3;             // 4 rows per store iteration
    const int scol = (lane & 7) * 8;        // 16B per lane

    for (int k = 0; k < 26; ++k) {
        const uint2* wf = Wf + (size_t)k * 1024 + lane;

        float acc[8][4];
#pragma unroll
        for (int nt = 0; nt < 8; ++nt)
#pragma unroll
            for (int j = 0; j < 4; ++j) acc[nt][j] = 0.0f;

#pragma unroll
        for (int s = 0; s < 4; ++s) {
            uint2 b[8];
#pragma unroll
            for (int nt = 0; nt < 8; ++nt)
                b[nt] = wf[(s * 8 + nt) * 32];
#pragma unroll
            for (int nt = 0; nt < 8; ++nt)
                mma_f16(acc[nt], A[s][0], A[s][1], A[s][2], A[s][3],
                        b[nt].x, b[nt].y);
        }

        if (k < KK) {
#pragma unroll
            for (int nt = 0; nt < 8; ++nt) {
                int colb = nt * 8 + gx * 2;
                *(__half2*)&stage[gy       * 72 + colb] =
                    __floats2half2_rn(acc[nt][0], acc[nt][1]);
                *(__half2*)&stage[(gy + 8) * 72 + colb] =
                    __floats2half2_rn(acc[nt][2], acc[nt][3]);
            }
            __syncwarp();
#pragma unroll
            for (int i = 0; i < 4; ++i) {
                int r = i * 4 + srow;
                int gn = n0 + m0 + r;
                uint4 v = *(const uint4*)&stage[r * 72 + scol];
                if (gn < N)
                    *(uint4*)&xk[(size_t)gn * (KK * C) + k * C + scol] = v;
            }
            __syncwarp();
        } else {
            int r0 = n0 + m0 + gy;
            int r1 = r0 + 8;
#pragma unroll
            for (int nt = 0; nt < 8; ++nt) {
                int colb = nt * 8 + gx * 2;
                float bi0 = bias[colb], bi1 = bias[colb + 1];
                if (r0 < N) {
                    rootout[(size_t)r0 * C + colb]     = acc[nt][0] + bi0;
                    rootout[(size_t)r0 * C + colb + 1] = acc[nt][1] + bi1;
                }
                if (r1 < N) {
                    rootout[(size_t)r1 * C + colb]     = acc[nt][2] + bi0;
                    rootout[(size_t)r1 * C + colb + 1] = acc[nt][3] + bi1;
                }
            }
        }
    }
}

// ---------------------------------------------------------------------------
// Aggregation pass: one warp per dst node, 2 edges per iteration
// (half-warp per edge, 4 channels per lane via uint2), software pipelined.
// (R9 baseline form — evict hints measured as regressions in R11/R14.)
// ---------------------------------------------------------------------------
struct EdgeStage {
    uint2 m;
    uint2 v00, v01, v10, v11;
};

__device__ __forceinline__ void stage_load(const __half* __restrict__ xkl,
                                           const uint2* __restrict__ emeta,
                                           int eidx, EdgeStage& st) {
    st.m = emeta[eidx];
    unsigned w = st.m.x;
    int s   = w & 131071;
    int i0a = (w >> 17) & 7, i1a = (w >> 20) & 7;
    int dx  = (w >> 23) & 1, dy  = (w >> 24) & 1;
    int t00 = i0a + 5 * i1a;
    const __half* base = xkl + (size_t)s * (KK * C);
    st.v00 = *(const uint2*)(base + t00 * C);
    st.v01 = *(const uint2*)(base + (t00 + dx) * C);
    st.v10 = *(const uint2*)(base + (t00 + 5 * dy) * C);
    st.v11 = *(const uint2*)(base + (t00 + 5 * dy + dx) * C);
}

__device__ __forceinline__ void stage_consume(const EdgeStage& st, float4& macc) {
    float2 f = __half22float2(*(const __half2*)&st.m.y);
    float w00 = (1.0f - f.x) * (1.0f - f.y);
    float w01 = f.x * (1.0f - f.y);
    float w10 = (1.0f - f.x) * f.y;
    float w11 = f.x * f.y;
    const __half2* p00 = (const __half2*)&st.v00;
    const __half2* p01 = (const __half2*)&st.v01;
    const __half2* p10 = (const __half2*)&st.v10;
    const __half2* p11 = (const __half2*)&st.v11;
    float2 a0 = __half22float2(p00[0]), a1 = __half22float2(p00[1]);
    float2 b0 = __half22float2(p01[0]), b1 = __half22float2(p01[1]);
    float2 c0 = __half22float2(p10[0]), c1 = __half22float2(p10[1]);
    float2 d0 = __half22float2(p11[0]), d1 = __half22float2(p11[1]);
    macc.x = fmaxf(macc.x, w00 * a0.x + w01 * b0.x + w10 * c0.x + w11 * d0.x);
    macc.y = fmaxf(macc.y, w00 * a0.y + w01 * b0.y + w10 * c0.y + w11 * d0.y);
    macc.z = fmaxf(macc.z, w00 * a1.x + w01 * b1.x + w10 * c1.x + w11 * d1.x);
    macc.w = fmaxf(macc.w, w00 * a1.y + w01 * b1.y + w10 * c1.y + w11 * d1.y);
}

__global__ void agg_kernel(const __half* __restrict__ xk,
                           const uint2* __restrict__ emeta,
                           const int* __restrict__ off,
                           const int* __restrict__ deg,
                           const float* __restrict__ aggbuf,
                           const float* __restrict__ rootout,
                           float* __restrict__ out, int N,
                           int mode, int do_relu) {
    int node = blockIdx.x * 8 + (threadIdx.x >> 5);
    int lane = threadIdx.x & 31;
    if (node >= N) return;

    int beg = off[node];
    int cnt = deg[node];
    const int half = lane >> 4;
    const int c4 = (lane & 15) * 4;

    float4 macc = make_float4(-INFINITY, -INFINITY, -INFINITY, -INFINITY);

    if (cnt > 0) {
        const __half* xkl = xk + c4;
        int npair = (cnt + 1) >> 1;
        EdgeStage stA;
        stage_load(xkl, emeta, beg + min(half, cnt - 1), stA);
        for (int i = 1; i < npair; ++i) {
            EdgeStage stB;
            stage_load(xkl, emeta, beg + min(2 * i + half, cnt - 1), stB);
            stage_consume(stA, macc);
            stA = stB;
        }
        stage_consume(stA, macc);
    }

    macc.x = fmaxf(macc.x, __shfl_xor_sync(0xffffffffu, macc.x, 16));
    macc.y = fmaxf(macc.y, __shfl_xor_sync(0xffffffffu, macc.y, 16));
    macc.z = fmaxf(macc.z, __shfl_xor_sync(0xffffffffu, macc.z, 16));
    macc.w = fmaxf(macc.w, __shfl_xor_sync(0xffffffffu, macc.w, 16));

    if (lane < 16) {
        size_t o = (size_t)node * C + c4;
        if (mode == 0) {
            *(float4*)&out[o] = macc;
        } else {
            float4 p = *(const float4*)&aggbuf[o];
            macc.x = fmaxf(macc.x, p.x);
            macc.y = fmaxf(macc.y, p.y);
            macc.z = fmaxf(macc.z, p.z);
            macc.w = fmaxf(macc.w, p.w);
            if (!isfinite(macc.x)) macc.x = 0.0f;
            if (!isfinite(macc.y)) macc.y = 0.0f;
            if (!isfinite(macc.z)) macc.z = 0.0f;
            if (!isfinite(macc.w)) macc.w = 0.0f;
            float4 r = *(const float4*)&rootout[o];
            macc.x += r.x; macc.y += r.y; macc.z += r.z; macc.w += r.w;
            if (do_relu) {
                macc.x = fmaxf(macc.x, 0.0f);
                macc.y = fmaxf(macc.y, 0.0f);
                macc.z = fmaxf(macc.z, 0.0f);
                macc.w = fmaxf(macc.w, 0.0f);
            }
            *(float4*)&out[o] = macc;
        }
    }
}

// ---------------------------------------------------------------------------
extern "C" void kernel_launch(void* const* d_in, const int* in_sizes, int n_in,
                              void* d_out, int out_size) {
    const float* x      = (const float*)d_in[0];
    const int*   ei     = (const int*)  d_in[1];
    const float* pseudo = (const float*)d_in[2];
    const float* W1     = (const float*)d_in[3];
    const float* root1  = (const float*)d_in[4];
    const float* bias1  = (const float*)d_in[5];
    const float* W2     = (const float*)d_in[6];
    const float* root2  = (const float*)d_in[7];
    const float* bias2  = (const float*)d_in[8];

    const int N = in_sizes[0] / C;
    const int E = in_sizes[1] / 2;
    const int* src = ei;
    const int* dst = ei + E;

    __half* xk;
    float *h, *rootout, *aggbuf;
    uint2 *wf1, *wf2, *emeta;
    int *deg, *cur, *off, *offp, *bsum;
    cudaGetSymbolAddress((void**)&xk,      g_xk);
    cudaGetSymbolAddress((void**)&h,       g_h);
    cudaGetSymbolAddress((void**)&rootout, g_rootout);
    cudaGetSymbolAddress((void**)&aggbuf,  g_aggbuf);
    cudaGetSymbolAddress((void**)&wf1,     g_wf1);
    cudaGetSymbolAddress((void**)&wf2,     g_wf2);
    cudaGetSymbolAddress((void**)&deg,     g_deg);
    cudaGetSymbolAddress((void**)&cur,     g_cursor);
    cudaGetSymbolAddress((void**)&off,     g_off);
    cudaGetSymbolAddress((void**)&offp,    g_offp);
    cudaGetSymbolAddress((void**)&bsum,    g_bsum);
    cudaGetSymbolAddress((void**)&emeta,   g_emeta);

    // fork/join resources (created once, on the uncaptured correctness call)
    static cudaStream_t s1 = nullptr;
    static cudaEvent_t evFork = nullptr, evSetup = nullptr;
    if (s1 == nullptr) {
        cudaStreamCreateWithFlags(&s1, cudaStreamNonBlocking);
        cudaEventCreateWithFlags(&evFork,  cudaEventDisableTiming);
        cudaEventCreateWithFlags(&evSetup, cudaEventDisableTiming);
    }

    const int total2N  = 2 * N;
    const int NB = (total2N + SCAN_B - 1) / SCAN_B;
    const int gemmBlocks = (N + 127) / 128;
    const int aggBlocks  = (N + 7) / 8;
    const int eBlocks    = (E + 255) / 256;
    const int wfTotal    = 26 * 4 * 8 * 32;

    // ---- fork: edge bucketing + cvt_w2 on s1; cvt_w1 + gemm1 on stream 0 ----
    cudaEventRecord(evFork, 0);
    cudaStreamWaitEvent(s1, evFork, 0);

    // stream 0: layer-1 weights + GEMM (independent of bucketing)
    cvt_w_kernel<<<(wfTotal + 255) / 256, 256>>>(W1, root1, wf1);
    gemm_xk_kernel<<<gemmBlocks, 256>>>(x, wf1, bias1, xk, rootout, N);

    // s1: edge bucketing chain + layer-2 weights
    zero_kernel<<<(total2N + 255) / 256, 256, 0, s1>>>(deg, cur, total2N);
    hist_kernel<<<eBlocks, 256, 0, s1>>>(dst, pseudo, deg, E, N);
    scan_local_kernel<<<NB, SCAN_B, 0, s1>>>(deg, offp, bsum, total2N);
    scan_bsum_kernel<<<1, 128, 0, s1>>>(bsum, NB);
    scan_add_kernel<<<(total2N + 255) / 256, 256, 0, s1>>>(offp, bsum, off, total2N);
    scatter_kernel<<<eBlocks, 256, 0, s1>>>(src, dst, pseudo, off, cur, emeta, E, N);
    cvt_w_kernel<<<(wfTotal + 255) / 256, 256, 0, s1>>>(W2, root2, wf2);
    cudaEventRecord(evSetup, s1);

    // join: aggregation needs emeta + xk
    cudaStreamWaitEvent(0, evSetup, 0);

    // ---- Layer 1 aggregation ----
    agg_kernel<<<aggBlocks, 256>>>(xk, emeta, off,     deg,     aggbuf, rootout, aggbuf, N, 0, 0);
    agg_kernel<<<aggBlocks, 256>>>(xk, emeta, off + N, deg + N, aggbuf, rootout, h,      N, 1, 1);

    // ---- Layer 2 ----
    gemm_xk_kernel<<<gemmBlocks, 256>>>(h, wf2, bias2, xk, rootout, N);
    agg_kernel<<<aggBlocks, 256>>>(xk, emeta, off,     deg,     aggbuf, rootout, aggbuf, N, 0, 0);
    agg_kernel<<<aggBlocks, 256>>>(xk, emeta, off + N, deg + N, aggbuf, rootout, (float*)d_out, N, 1, 0);
}

// round 16
// speedup vs baseline: 1.1685x; 1.1685x over previous
#include <cuda_runtime.h>
#include <cuda_fp16.h>
#include <math.h>

// Problem-fixed sizes: N=50000, E=1600000, C=64, K=5 (25 kernels)
#define MAXN 50176
#define MAXE 1600000
#define C 64
#define KK 25
#define SCAN_B 1024

// Scratch. xk layout: [n][k][64] fp16 (single buffer).
static __device__ __half g_xk[(size_t)MAXN * KK * C];    // 160MB
static __device__ float  g_h[(size_t)MAXN * C];
static __device__ float  g_rootout[(size_t)MAXN * C];
static __device__ uint2  g_wf1[26 * 4 * 8 * 32];
static __device__ uint2  g_wf2[26 * 4 * 8 * 32];
static __device__ int    g_deg[2 * MAXN];
static __device__ int    g_cursor[2 * MAXN];
static __device__ int    g_off[2 * MAXN];
static __device__ int    g_offp[2 * MAXN];
static __device__ int    g_bsum[128];
static __device__ uint2  g_emeta[MAXE];

// ---------------------------------------------------------------------------
__device__ __forceinline__ void mma_f16(float* c,
                                        unsigned a0, unsigned a1, unsigned a2, unsigned a3,
                                        unsigned b0, unsigned b1) {
    asm("mma.sync.aligned.m16n8k16.row.col.f32.f16.f16.f32 "
        "{%0,%1,%2,%3}, {%4,%5,%6,%7}, {%8,%9}, {%0,%1,%2,%3};"
        : "+f"(c[0]), "+f"(c[1]), "+f"(c[2]), "+f"(c[3])
        : "r"(a0), "r"(a1), "r"(a2), "r"(a3), "r"(b0), "r"(b1));
}

// ---------------------------------------------------------------------------
__global__ void cvt_w_kernel(const float* __restrict__ W, const float* __restrict__ root,
                             uint2* __restrict__ frag) {
    int idx = blockIdx.x * blockDim.x + threadIdx.x;
    if (idx >= 26 * 4 * 8 * 32) return;
    int lane = idx & 31;
    int nt   = (idx >> 5) & 7;
    int s    = (idx >> 8) & 3;
    int k    = idx >> 10;
    int gy = lane >> 2, gx = lane & 3;
    int o = nt * 8 + gy;
    int i = s * 16 + 2 * gx;
    const float* src = (k < KK) ? (W + (size_t)k * 4096) : root;
    __half2 b0 = __floats2half2_rn(src[i * 64 + o],       src[(i + 1) * 64 + o]);
    __half2 b1 = __floats2half2_rn(src[(i + 8) * 64 + o], src[(i + 9) * 64 + o]);
    frag[idx] = make_uint2(*(unsigned*)&b0, *(unsigned*)&b1);
}

// ---------------------------------------------------------------------------
// Edge bucketing by (pass, dst)
// ---------------------------------------------------------------------------
__device__ __forceinline__ int edge_pass(float u1) {
    float v1 = u1 * 4.0f;
    int i1 = (int)floorf(v1);
    int i1a = min(max(i1, 0), 4);
    return (i1a <= 1) ? 0 : 1;
}

__global__ void zero_kernel(int* __restrict__ deg, int* __restrict__ cur, int total) {
    int i = blockIdx.x * blockDim.x + threadIdx.x;
    if (i < total) { deg[i] = 0; cur[i] = 0; }
}

__global__ void hist_kernel(const int* __restrict__ dst, const float* __restrict__ pseudo,
                            int* __restrict__ deg, int E, int N) {
    int e = blockIdx.x * blockDim.x + threadIdx.x;
    if (e < E) {
        int p = edge_pass(pseudo[2 * e + 1]);
        atomicAdd(&deg[p * N + dst[e]], 1);
    }
}

__global__ void scan_local_kernel(const int* __restrict__ deg, int* __restrict__ offp,
                                  int* __restrict__ bsum, int total) {
    __shared__ int s[SCAN_B];
    int tid = threadIdx.x;
    int g = blockIdx.x * SCAN_B + tid;
    int v = (g < total) ? deg[g] : 0;
    s[tid] = v;
    __syncthreads();
#pragma unroll
    for (int o = 1; o < SCAN_B; o <<= 1) {
        int t = (tid >= o) ? s[tid - o] : 0;
        __syncthreads();
        s[tid] += t;
        __syncthreads();
    }
    if (g < total) offp[g] = s[tid] - v;
    if (tid == SCAN_B - 1) bsum[blockIdx.x] = s[tid];
}

__global__ void scan_bsum_kernel(int* __restrict__ bsum, int NB) {
    __shared__ int s[128];
    int tid = threadIdx.x;
    int v = (tid < NB) ? bsum[tid] : 0;
    s[tid] = v;
    __syncthreads();
#pragma unroll
    for (int o = 1; o < 128; o <<= 1) {
        int t = (tid >= o) ? s[tid - o] : 0;
        __syncthreads();
        s[tid] += t;
        __syncthreads();
    }
    if (tid < NB) bsum[tid] = s[tid] - v;
}

__global__ void scan_add_kernel(const int* __restrict__ offp, const int* __restrict__ bsum,
                                int* __restrict__ off, int total) {
    int i = blockIdx.x * blockDim.x + threadIdx.x;
    if (i < total) off[i] = offp[i] + bsum[i / SCAN_B];
}

__global__ void scatter_kernel(const int* __restrict__ src, const int* __restrict__ dst,
                               const float* __restrict__ pseudo,
                               const int* __restrict__ off, int* __restrict__ cur,
                               uint2* __restrict__ emeta, int E, int N) {
    int e = blockIdx.x * blockDim.x + threadIdx.x;
    if (e >= E) return;
    int d = dst[e];
    int s = src[e];
    float v0 = pseudo[2 * e + 0] * 4.0f;
    float v1 = pseudo[2 * e + 1] * 4.0f;
    float b0f = floorf(v0), b1f = floorf(v1);
    float f0 = v0 - b0f, f1 = v1 - b1f;
    int i0 = (int)b0f, i1 = (int)b1f;
    int i0a = min(max(i0, 0), 4);
    int i0b = min(max(i0 + 1, 0), 4);
    int i1a = min(max(i1, 0), 4);
    int i1b = min(max(i1 + 1, 0), 4);
    int p = (i1a <= 1) ? 0 : 1;

    unsigned w0 = (unsigned)s | ((unsigned)i0a << 17) | ((unsigned)i1a << 20)
                | ((unsigned)(i0b - i0a) << 23) | ((unsigned)(i1b - i1a) << 24);
    __half2 fh = __floats2half2_rn(f0, f1);
    unsigned w1 = *(unsigned*)&fh;

    int pos = off[p * N + d] + atomicAdd(&cur[p * N + d], 1);
    emeta[pos] = make_uint2(w0, w1);
}

// ---------------------------------------------------------------------------
// GEMM (fp16 MMA m16n8k16): 256-node tile, 26 matrices (R9 config — M=128
// regressed in R15: W-frag reload dominates). B frags from packed global
// (L1-resident); A frags register-resident across all 26 matrices.
// xk stores staged through smem -> coalesced 128B-row STG.128.
// ---------------------------------------------------------------------------
__global__ void __launch_bounds__(256, 2)
gemm_xk_kernel(const float* __restrict__ x,
               const uint2* __restrict__ Wf,
               const float* __restrict__ bias,
               __half* __restrict__ xk,
               float* __restrict__ rootout, int N) {
    __shared__ __half xs[256 * 72];
    const int tid  = threadIdx.x;
    const int lane = tid & 31;
    const int warp = tid >> 5;
    const int n0   = blockIdx.x * 256;

    for (int t = tid; t < 256 * 16; t += 256) {
        int r = t >> 4, c = (t & 15) * 4;
        int n = n0 + r;
        float4 v = (n < N) ? *(const float4*)&x[(size_t)n * C + c]
                           : make_float4(0.f, 0.f, 0.f, 0.f);
        __half2* p = (__half2*)&xs[r * 72 + c];
        p[0] = __floats2half2_rn(v.x, v.y);
        p[1] = __floats2half2_rn(v.z, v.w);
    }
    __syncthreads();

    const int gy = lane >> 2;
    const int gx = lane & 3;
    const int m0 = warp * 32;

    unsigned A[4][2][4];
#pragma unroll
    for (int s = 0; s < 4; ++s) {
        int k0 = s * 16;
#pragma unroll
        for (int mt = 0; mt < 2; ++mt) {
            int mr = m0 + mt * 16;
            A[s][mt][0] = *(const unsigned*)&xs[(mr + gy)     * 72 + k0 + 2 * gx];
            A[s][mt][1] = *(const unsigned*)&xs[(mr + gy + 8) * 72 + k0 + 2 * gx];
            A[s][mt][2] = *(const unsigned*)&xs[(mr + gy)     * 72 + k0 + 2 * gx + 8];
            A[s][mt][3] = *(const unsigned*)&xs[(mr + gy + 8) * 72 + k0 + 2 * gx + 8];
        }
    }
    __syncthreads();   // x tile fully consumed; xs becomes per-warp store stage

    __half* stage = &xs[warp * 32 * 72];
    const int srow = lane >> 3;
    const int scol = (lane & 7) * 8;

    for (int k = 0; k < 26; ++k) {
        const uint2* wf = Wf + (size_t)k * 1024 + lane;

        float acc[2][8][4];
#pragma unroll
        for (int mt = 0; mt < 2; ++mt)
#pragma unroll
            for (int nt = 0; nt < 8; ++nt)
#pragma unroll
                for (int j = 0; j < 4; ++j) acc[mt][nt][j] = 0.0f;

#pragma unroll
        for (int s = 0; s < 4; ++s) {
            uint2 b[8];
#pragma unroll
            for (int nt = 0; nt < 8; ++nt)
                b[nt] = wf[(s * 8 + nt) * 32];
#pragma unroll
            for (int nt = 0; nt < 8; ++nt) {
                mma_f16(acc[0][nt], A[s][0][0], A[s][0][1], A[s][0][2], A[s][0][3],
                        b[nt].x, b[nt].y);
                mma_f16(acc[1][nt], A[s][1][0], A[s][1][1], A[s][1][2], A[s][1][3],
                        b[nt].x, b[nt].y);
            }
        }

        if (k < KK) {
#pragma unroll
            for (int mt = 0; mt < 2; ++mt) {
#pragma unroll
                for (int nt = 0; nt < 8; ++nt) {
                    int colb = nt * 8 + gx * 2;
                    *(__half2*)&stage[(mt * 16 + gy)     * 72 + colb] =
                        __floats2half2_rn(acc[mt][nt][0], acc[mt][nt][1]);
                    *(__half2*)&stage[(mt * 16 + gy + 8) * 72 + colb] =
                        __floats2half2_rn(acc[mt][nt][2], acc[mt][nt][3]);
                }
            }
            __syncwarp();
#pragma unroll
            for (int i = 0; i < 8; ++i) {
                int r = i * 4 + srow;
                int gn = n0 + m0 + r;
                uint4 v = *(const uint4*)&stage[r * 72 + scol];
                if (gn < N)
                    *(uint4*)&xk[(size_t)gn * (KK * C) + k * C + scol] = v;
            }
            __syncwarp();
        } else {
#pragma unroll
            for (int mt = 0; mt < 2; ++mt) {
                int r0 = n0 + m0 + mt * 16 + gy;
                int r1 = r0 + 8;
#pragma unroll
                for (int nt = 0; nt < 8; ++nt) {
                    int colb = nt * 8 + gx * 2;
                    float bi0 = bias[colb], bi1 = bias[colb + 1];
                    if (r0 < N) {
                        rootout[(size_t)r0 * C + colb]     = acc[mt][nt][0] + bi0;
                        rootout[(size_t)r0 * C + colb + 1] = acc[mt][nt][1] + bi1;
                    }
                    if (r1 < N) {
                        rootout[(size_t)r1 * C + colb]     = acc[mt][nt][2] + bi0;
                        rootout[(size_t)r1 * C + colb + 1] = acc[mt][nt][3] + bi1;
                    }
                }
            }
        }
    }
}

// ---------------------------------------------------------------------------
// Fused aggregation: ONE kernel per layer. Each warp processes its node's
// pass-0 segment then its pass-1 segment (same 2-edge pipelined inner loop),
// then finalizes directly: empty->0, + rootout, opt relu. No aggbuf.
// ---------------------------------------------------------------------------
struct EdgeStage {
    uint2 m;
    uint2 v00, v01, v10, v11;
};

__device__ __forceinline__ void stage_load(const __half* __restrict__ xkl,
                                           const uint2* __restrict__ emeta,
                                           int eidx, EdgeStage& st) {
    st.m = emeta[eidx];
    unsigned w = st.m.x;
    int s   = w & 131071;
    int i0a = (w >> 17) & 7, i1a = (w >> 20) & 7;
    int dx  = (w >> 23) & 1, dy  = (w >> 24) & 1;
    int t00 = i0a + 5 * i1a;
    const __half* base = xkl + (size_t)s * (KK * C);
    st.v00 = *(const uint2*)(base + t00 * C);
    st.v01 = *(const uint2*)(base + (t00 + dx) * C);
    st.v10 = *(const uint2*)(base + (t00 + 5 * dy) * C);
    st.v11 = *(const uint2*)(base + (t00 + 5 * dy + dx) * C);
}

__device__ __forceinline__ void stage_consume(const EdgeStage& st, float4& macc) {
    float2 f = __half22float2(*(const __half2*)&st.m.y);
    float w00 = (1.0f - f.x) * (1.0f - f.y);
    float w01 = f.x * (1.0f - f.y);
    float w10 = (1.0f - f.x) * f.y;
    float w11 = f.x * f.y;
    const __half2* p00 = (const __half2*)&st.v00;
    const __half2* p01 = (const __half2*)&st.v01;
    const __half2* p10 = (const __half2*)&st.v10;
    const __half2* p11 = (const __half2*)&st.v11;
    float2 a0 = __half22float2(p00[0]), a1 = __half22float2(p00[1]);
    float2 b0 = __half22float2(p01[0]), b1 = __half22float2(p01[1]);
    float2 c0 = __half22float2(p10[0]), c1 = __half22float2(p10[1]);
    float2 d0 = __half22float2(p11[0]), d1 = __half22float2(p11[1]);
    macc.x = fmaxf(macc.x, w00 * a0.x + w01 * b0.x + w10 * c0.x + w11 * d0.x);
    macc.y = fmaxf(macc.y, w00 * a0.y + w01 * b0.y + w10 * c0.y + w11 * d0.y);
    macc.z = fmaxf(macc.z, w00 * a1.x + w01 * b1.x + w10 * c1.x + w11 * d1.x);
    macc.w = fmaxf(macc.w, w00 * a1.y + w01 * b1.y + w10 * c1.y + w11 * d1.y);
}

__global__ void agg_fused_kernel(const __half* __restrict__ xk,
                                 const uint2* __restrict__ emeta,
                                 const int* __restrict__ off,
                                 const int* __restrict__ deg,
                                 const float* __restrict__ rootout,
                                 float* __restrict__ out, int N,
                                 int do_relu) {
    int node = blockIdx.x * 8 + (threadIdx.x >> 5);
    int lane = threadIdx.x & 31;
    if (node >= N) return;

    const int half = lane >> 4;
    const int c4 = (lane & 15) * 4;
    const __half* xkl = xk + c4;

    float4 macc = make_float4(-INFINITY, -INFINITY, -INFINITY, -INFINITY);

#pragma unroll
    for (int p = 0; p < 2; ++p) {
        int beg = off[p * N + node];
        int cnt = deg[p * N + node];
        if (cnt > 0) {
            int npair = (cnt + 1) >> 1;
            EdgeStage stA;
            stage_load(xkl, emeta, beg + min(half, cnt - 1), stA);
            for (int i = 1; i < npair; ++i) {
                EdgeStage stB;
                stage_load(xkl, emeta, beg + min(2 * i + half, cnt - 1), stB);
                stage_consume(stA, macc);
                stA = stB;
            }
            stage_consume(stA, macc);
        }
    }

    macc.x = fmaxf(macc.x, __shfl_xor_sync(0xffffffffu, macc.x, 16));
    macc.y = fmaxf(macc.y, __shfl_xor_sync(0xffffffffu, macc.y, 16));
    macc.z = fmaxf(macc.z, __shfl_xor_sync(0xffffffffu, macc.z, 16));
    macc.w = fmaxf(macc.w, __shfl_xor_sync(0xffffffffu, macc.w, 16));

    if (lane < 16) {
        size_t o = (size_t)node * C + c4;
        if (!isfinite(macc.x)) macc.x = 0.0f;   // empty node -> 0 (PyG convention)
        if (!isfinite(macc.y)) macc.y = 0.0f;
        if (!isfinite(macc.z)) macc.z = 0.0f;
        if (!isfinite(macc.w)) macc.w = 0.0f;
        float4 r = *(const float4*)&rootout[o];
        macc.x += r.x; macc.y += r.y; macc.z += r.z; macc.w += r.w;
        if (do_relu) {
            macc.x = fmaxf(macc.x, 0.0f);
            macc.y = fmaxf(macc.y, 0.0f);
            macc.z = fmaxf(macc.z, 0.0f);
            macc.w = fmaxf(macc.w, 0.0f);
        }
        *(float4*)&out[o] = macc;
    }
}

// ---------------------------------------------------------------------------
extern "C" void kernel_launch(void* const* d_in, const int* in_sizes, int n_in,
                              void* d_out, int out_size) {
    const float* x      = (const float*)d_in[0];
    const int*   ei     = (const int*)  d_in[1];
    const float* pseudo = (const float*)d_in[2];
    const float* W1     = (const float*)d_in[3];
    const float* root1  = (const float*)d_in[4];
    const float* bias1  = (const float*)d_in[5];
    const float* W2     = (const float*)d_in[6];
    const float* root2  = (const float*)d_in[7];
    const float* bias2  = (const float*)d_in[8];

    const int N = in_sizes[0] / C;
    const int E = in_sizes[1] / 2;
    const int* src = ei;
    const int* dst = ei + E;

    __half* xk;
    float *h, *rootout;
    uint2 *wf1, *wf2, *emeta;
    int *deg, *cur, *off, *offp, *bsum;
    cudaGetSymbolAddress((void**)&xk,      g_xk);
    cudaGetSymbolAddress((void**)&h,       g_h);
    cudaGetSymbolAddress((void**)&rootout, g_rootout);
    cudaGetSymbolAddress((void**)&wf1,     g_wf1);
    cudaGetSymbolAddress((void**)&wf2,     g_wf2);
    cudaGetSymbolAddress((void**)&deg,     g_deg);
    cudaGetSymbolAddress((void**)&cur,     g_cursor);
    cudaGetSymbolAddress((void**)&off,     g_off);
    cudaGetSymbolAddress((void**)&offp,    g_offp);
    cudaGetSymbolAddress((void**)&bsum,    g_bsum);
    cudaGetSymbolAddress((void**)&emeta,   g_emeta);

    // fork/join resources (created once, on the uncaptured correctness call)
    static cudaStream_t s1 = nullptr;
    static cudaEvent_t evFork = nullptr, evSetup = nullptr;
    if (s1 == nullptr) {
        cudaStreamCreateWithFlags(&s1, cudaStreamNonBlocking);
        cudaEventCreateWithFlags(&evFork,  cudaEventDisableTiming);
        cudaEventCreateWithFlags(&evSetup, cudaEventDisableTiming);
    }

    const int total2N  = 2 * N;
    const int NB = (total2N + SCAN_B - 1) / SCAN_B;
    const int gemmBlocks = (N + 255) / 256;
    const int aggBlocks  = (N + 7) / 8;
    const int eBlocks    = (E + 255) / 256;
    const int wfTotal    = 26 * 4 * 8 * 32;

    // ---- fork: edge bucketing + cvt_w2 on s1; cvt_w1 + gemm1 on stream 0 ----
    cudaEventRecord(evFork, 0);
    cudaStreamWaitEvent(s1, evFork, 0);

    // stream 0: layer-1 weights + GEMM (independent of bucketing)
    cvt_w_kernel<<<(wfTotal + 255) / 256, 256>>>(W1, root1, wf1);
    gemm_xk_kernel<<<gemmBlocks, 256>>>(x, wf1, bias1, xk, rootout, N);

    // s1: edge bucketing chain + layer-2 weights
    zero_kernel<<<(total2N + 255) / 256, 256, 0, s1>>>(deg, cur, total2N);
    hist_kernel<<<eBlocks, 256, 0, s1>>>(dst, pseudo, deg, E, N);
    scan_local_kernel<<<NB, SCAN_B, 0, s1>>>(deg, offp, bsum, total2N);
    scan_bsum_kernel<<<1, 128, 0, s1>>>(bsum, NB);
    scan_add_kernel<<<(total2N + 255) / 256, 256, 0, s1>>>(offp, bsum, off, total2N);
    scatter_kernel<<<eBlocks, 256, 0, s1>>>(src, dst, pseudo, off, cur, emeta, E, N);
    cvt_w_kernel<<<(wfTotal + 255) / 256, 256, 0, s1>>>(W2, root2, wf2);
    cudaEventRecord(evSetup, s1);

    // join: aggregation needs emeta + xk
    cudaStreamWaitEvent(0, evSetup, 0);

    // ---- Layer 1: fused aggregation + finalize ----
    agg_fused_kernel<<<aggBlocks, 256>>>(xk, emeta, off, deg, rootout, h, N, 1);

    // ---- Layer 2 ----
    gemm_xk_kernel<<<gemmBlocks, 256>>>(h, wf2, bias2, xk, rootout, N);
    agg_fused_kernel<<<aggBlocks, 256>>>(xk, emeta, off, deg, rootout, (float*)d_out, N, 0);
}

// round 17
// speedup vs baseline: 1.1984x; 1.0255x over previous
#include <cuda_runtime.h>
#include <cuda_fp16.h>
#include <math.h>

// Problem-fixed sizes: N=50000, E=1600000, C=64, K=5 (25 kernels)
#define MAXN 50176
#define MAXE 1600000
#define C 64
#define KK 25
#define SCAN_B 1024

// Scratch. xk layout: [n][k][64] fp16 (single buffer).
static __device__ __half g_xk[(size_t)MAXN * KK * C];    // 160MB
static __device__ float  g_h[(size_t)MAXN * C];
static __device__ float  g_rootout[(size_t)MAXN * C];
static __device__ uint2  g_wf1[26 * 4 * 8 * 32];
static __device__ uint2  g_wf2[26 * 4 * 8 * 32];
static __device__ int    g_deg[MAXN];
static __device__ int    g_cursor[MAXN];
static __device__ int    g_off[MAXN];
static __device__ int    g_offp[MAXN];
static __device__ int    g_bsum[64];
static __device__ uint2  g_emeta[MAXE];

// ---------------------------------------------------------------------------
__device__ __forceinline__ void mma_f16(float* c,
                                        unsigned a0, unsigned a1, unsigned a2, unsigned a3,
                                        unsigned b0, unsigned b1) {
    asm("mma.sync.aligned.m16n8k16.row.col.f32.f16.f16.f32 "
        "{%0,%1,%2,%3}, {%4,%5,%6,%7}, {%8,%9}, {%0,%1,%2,%3};"
        : "+f"(c[0]), "+f"(c[1]), "+f"(c[2]), "+f"(c[3])
        : "r"(a0), "r"(a1), "r"(a2), "r"(a3), "r"(b0), "r"(b1));
}

// ---------------------------------------------------------------------------
__global__ void cvt_w_kernel(const float* __restrict__ W, const float* __restrict__ root,
                             uint2* __restrict__ frag) {
    int idx = blockIdx.x * blockDim.x + threadIdx.x;
    if (idx >= 26 * 4 * 8 * 32) return;
    int lane = idx & 31;
    int nt   = (idx >> 5) & 7;
    int s    = (idx >> 8) & 3;
    int k    = idx >> 10;
    int gy = lane >> 2, gx = lane & 3;
    int o = nt * 8 + gy;
    int i = s * 16 + 2 * gx;
    const float* src = (k < KK) ? (W + (size_t)k * 4096) : root;
    __half2 b0 = __floats2half2_rn(src[i * 64 + o],       src[(i + 1) * 64 + o]);
    __half2 b1 = __floats2half2_rn(src[(i + 8) * 64 + o], src[(i + 9) * 64 + o]);
    frag[idx] = make_uint2(*(unsigned*)&b0, *(unsigned*)&b1);
}

// ---------------------------------------------------------------------------
// Edge bucketing by dst only (pass-split removed: phase separation proved
// worthless in R7/R16; single contiguous segment per node).
// ---------------------------------------------------------------------------
__global__ void zero_kernel(int* __restrict__ deg, int* __restrict__ cur, int total) {
    int i = blockIdx.x * blockDim.x + threadIdx.x;
    if (i < total) { deg[i] = 0; cur[i] = 0; }
}

__global__ void hist_kernel(const int* __restrict__ dst, int* __restrict__ deg, int E) {
    int e = blockIdx.x * blockDim.x + threadIdx.x;
    if (e < E) atomicAdd(&deg[dst[e]], 1);
}

__global__ void scan_local_kernel(const int* __restrict__ deg, int* __restrict__ offp,
                                  int* __restrict__ bsum, int total) {
    __shared__ int s[SCAN_B];
    int tid = threadIdx.x;
    int g = blockIdx.x * SCAN_B + tid;
    int v = (g < total) ? deg[g] : 0;
    s[tid] = v;
    __syncthreads();
#pragma unroll
    for (int o = 1; o < SCAN_B; o <<= 1) {
        int t = (tid >= o) ? s[tid - o] : 0;
        __syncthreads();
        s[tid] += t;
        __syncthreads();
    }
    if (g < total) offp[g] = s[tid] - v;
    if (tid == SCAN_B - 1) bsum[blockIdx.x] = s[tid];
}

__global__ void scan_bsum_kernel(int* __restrict__ bsum, int NB) {
    __shared__ int s[64];
    int tid = threadIdx.x;
    int v = (tid < NB) ? bsum[tid] : 0;
    s[tid] = v;
    __syncthreads();
#pragma unroll
    for (int o = 1; o < 64; o <<= 1) {
        int t = (tid >= o) ? s[tid - o] : 0;
        __syncthreads();
        s[tid] += t;
        __syncthreads();
    }
    if (tid < NB) bsum[tid] = s[tid] - v;
}

__global__ void scan_add_kernel(const int* __restrict__ offp, const int* __restrict__ bsum,
                                int* __restrict__ off, int total) {
    int i = blockIdx.x * blockDim.x + threadIdx.x;
    if (i < total) off[i] = offp[i] + bsum[i / SCAN_B];
}

__global__ void scatter_kernel(const int* __restrict__ src, const int* __restrict__ dst,
                               const float* __restrict__ pseudo,
                               const int* __restrict__ off, int* __restrict__ cur,
                               uint2* __restrict__ emeta, int E) {
    int e = blockIdx.x * blockDim.x + threadIdx.x;
    if (e >= E) return;
    int d = dst[e];
    int s = src[e];
    float v0 = pseudo[2 * e + 0] * 4.0f;
    float v1 = pseudo[2 * e + 1] * 4.0f;
    float b0f = floorf(v0), b1f = floorf(v1);
    float f0 = v0 - b0f, f1 = v1 - b1f;
    int i0 = (int)b0f, i1 = (int)b1f;
    int i0a = min(max(i0, 0), 4);
    int i0b = min(max(i0 + 1, 0), 4);
    int i1a = min(max(i1, 0), 4);
    int i1b = min(max(i1 + 1, 0), 4);

    unsigned w0 = (unsigned)s | ((unsigned)i0a << 17) | ((unsigned)i1a << 20)
                | ((unsigned)(i0b - i0a) << 23) | ((unsigned)(i1b - i1a) << 24);
    __half2 fh = __floats2half2_rn(f0, f1);
    unsigned w1 = *(unsigned*)&fh;

    int pos = off[d] + atomicAdd(&cur[d], 1);
    emeta[pos] = make_uint2(w0, w1);
}

// ---------------------------------------------------------------------------
// GEMM (fp16 MMA m16n8k16): 256-node tile, 26 matrices (config optimum —
// M=128 regressed in R15). B frags from packed global (L1-resident);
// A frags register-resident; stores staged through smem -> STG.128.
// ---------------------------------------------------------------------------
__global__ void __launch_bounds__(256, 2)
gemm_xk_kernel(const float* __restrict__ x,
               const uint2* __restrict__ Wf,
               const float* __restrict__ bias,
               __half* __restrict__ xk,
               float* __restrict__ rootout, int N) {
    __shared__ __half xs[256 * 72];
    const int tid  = threadIdx.x;
    const int lane = tid & 31;
    const int warp = tid >> 5;
    const int n0   = blockIdx.x * 256;

    for (int t = tid; t < 256 * 16; t += 256) {
        int r = t >> 4, c = (t & 15) * 4;
        int n = n0 + r;
        float4 v = (n < N) ? *(const float4*)&x[(size_t)n * C + c]
                           : make_float4(0.f, 0.f, 0.f, 0.f);
        __half2* p = (__half2*)&xs[r * 72 + c];
        p[0] = __floats2half2_rn(v.x, v.y);
        p[1] = __floats2half2_rn(v.z, v.w);
    }
    __syncthreads();

    const int gy = lane >> 2;
    const int gx = lane & 3;
    const int m0 = warp * 32;

    unsigned A[4][2][4];
#pragma unroll
    for (int s = 0; s < 4; ++s) {
        int k0 = s * 16;
#pragma unroll
        for (int mt = 0; mt < 2; ++mt) {
            int mr = m0 + mt * 16;
            A[s][mt][0] = *(const unsigned*)&xs[(mr + gy)     * 72 + k0 + 2 * gx];
            A[s][mt][1] = *(const unsigned*)&xs[(mr + gy + 8) * 72 + k0 + 2 * gx];
            A[s][mt][2] = *(const unsigned*)&xs[(mr + gy)     * 72 + k0 + 2 * gx + 8];
            A[s][mt][3] = *(const unsigned*)&xs[(mr + gy + 8) * 72 + k0 + 2 * gx + 8];
        }
    }
    __syncthreads();   // x tile fully consumed; xs becomes per-warp store stage

    __half* stage = &xs[warp * 32 * 72];
    const int srow = lane >> 3;
    const int scol = (lane & 7) * 8;

    for (int k = 0; k < 26; ++k) {
        const uint2* wf = Wf + (size_t)k * 1024 + lane;

        float acc[2][8][4];
#pragma unroll
        for (int mt = 0; mt < 2; ++mt)
#pragma unroll
            for (int nt = 0; nt < 8; ++nt)
#pragma unroll
                for (int j = 0; j < 4; ++j) acc[mt][nt][j] = 0.0f;

#pragma unroll
        for (int s = 0; s < 4; ++s) {
            uint2 b[8];
#pragma unroll
            for (int nt = 0; nt < 8; ++nt)
                b[nt] = wf[(s * 8 + nt) * 32];
#pragma unroll
            for (int nt = 0; nt < 8; ++nt) {
                mma_f16(acc[0][nt], A[s][0][0], A[s][0][1], A[s][0][2], A[s][0][3],
                        b[nt].x, b[nt].y);
                mma_f16(acc[1][nt], A[s][1][0], A[s][1][1], A[s][1][2], A[s][1][3],
                        b[nt].x, b[nt].y);
            }
        }

        if (k < KK) {
#pragma unroll
            for (int mt = 0; mt < 2; ++mt) {
#pragma unroll
                for (int nt = 0; nt < 8; ++nt) {
                    int colb = nt * 8 + gx * 2;
                    *(__half2*)&stage[(mt * 16 + gy)     * 72 + colb] =
                        __floats2half2_rn(acc[mt][nt][0], acc[mt][nt][1]);
                    *(__half2*)&stage[(mt * 16 + gy + 8) * 72 + colb] =
                        __floats2half2_rn(acc[mt][nt][2], acc[mt][nt][3]);
                }
            }
            __syncwarp();
#pragma unroll
            for (int i = 0; i < 8; ++i) {
                int r = i * 4 + srow;
                int gn = n0 + m0 + r;
                uint4 v = *(const uint4*)&stage[r * 72 + scol];
                if (gn < N)
                    *(uint4*)&xk[(size_t)gn * (KK * C) + k * C + scol] = v;
            }
            __syncwarp();
        } else {
#pragma unroll
            for (int mt = 0; mt < 2; ++mt) {
                int r0 = n0 + m0 + mt * 16 + gy;
                int r1 = r0 + 8;
#pragma unroll
                for (int nt = 0; nt < 8; ++nt) {
                    int colb = nt * 8 + gx * 2;
                    float bi0 = bias[colb], bi1 = bias[colb + 1];
                    if (r0 < N) {
                        rootout[(size_t)r0 * C + colb]     = acc[mt][nt][0] + bi0;
                        rootout[(size_t)r0 * C + colb + 1] = acc[mt][nt][1] + bi1;
                    }
                    if (r1 < N) {
                        rootout[(size_t)r1 * C + colb]     = acc[mt][nt][2] + bi0;
                        rootout[(size_t)r1 * C + colb + 1] = acc[mt][nt][3] + bi1;
                    }
                }
            }
        }
    }
}

// ---------------------------------------------------------------------------
// Fused aggregation: one kernel per layer, one contiguous edge segment per
// node. 2 edges/iter (half-warp per edge, 4 ch/lane via uint2), software
// pipelined; finalize (empty->0, +rootout, opt relu) inline.
// ---------------------------------------------------------------------------
struct EdgeStage {
    uint2 m;
    uint2 v00, v01, v10, v11;
};

__device__ __forceinline__ void stage_load(const __half* __restrict__ xkl,
                                           const uint2* __restrict__ emeta,
                                           int eidx, EdgeStage& st) {
    st.m = emeta[eidx];
    unsigned w = st.m.x;
    int s   = w & 131071;
    int i0a = (w >> 17) & 7, i1a = (w >> 20) & 7;
    int dx  = (w >> 23) & 1, dy  = (w >> 24) & 1;
    int t00 = i0a + 5 * i1a;
    const __half* base = xkl + (size_t)s * (KK * C);
    st.v00 = *(const uint2*)(base + t00 * C);
    st.v01 = *(const uint2*)(base + (t00 + dx) * C);
    st.v10 = *(const uint2*)(base + (t00 + 5 * dy) * C);
    st.v11 = *(const uint2*)(base + (t00 + 5 * dy + dx) * C);
}

__device__ __forceinline__ void stage_consume(const EdgeStage& st, float4& macc) {
    float2 f = __half22float2(*(const __half2*)&st.m.y);
    float w00 = (1.0f - f.x) * (1.0f - f.y);
    float w01 = f.x * (1.0f - f.y);
    float w10 = (1.0f - f.x) * f.y;
    float w11 = f.x * f.y;
    const __half2* p00 = (const __half2*)&st.v00;
    const __half2* p01 = (const __half2*)&st.v01;
    const __half2* p10 = (const __half2*)&st.v10;
    const __half2* p11 = (const __half2*)&st.v11;
    float2 a0 = __half22float2(p00[0]), a1 = __half22float2(p00[1]);
    float2 b0 = __half22float2(p01[0]), b1 = __half22float2(p01[1]);
    float2 c0 = __half22float2(p10[0]), c1 = __half22float2(p10[1]);
    float2 d0 = __half22float2(p11[0]), d1 = __half22float2(p11[1]);
    macc.x = fmaxf(macc.x, w00 * a0.x + w01 * b0.x + w10 * c0.x + w11 * d0.x);
    macc.y = fmaxf(macc.y, w00 * a0.y + w01 * b0.y + w10 * c0.y + w11 * d0.y);
    macc.z = fmaxf(macc.z, w00 * a1.x + w01 * b1.x + w10 * c1.x + w11 * d1.x);
    macc.w = fmaxf(macc.w, w00 * a1.y + w01 * b1.y + w10 * c1.y + w11 * d1.y);
}

__global__ void agg_fused_kernel(const __half* __restrict__ xk,
                                 const uint2* __restrict__ emeta,
                                 const int* __restrict__ off,
                                 const int* __restrict__ deg,
                                 const float* __restrict__ rootout,
                                 float* __restrict__ out, int N,
                                 int do_relu) {
    int node = blockIdx.x * 8 + (threadIdx.x >> 5);
    int lane = threadIdx.x & 31;
    if (node >= N) return;

    const int half = lane >> 4;
    const int c4 = (lane & 15) * 4;
    const __half* xkl = xk + c4;

    int beg = off[node];
    int cnt = deg[node];

    float4 macc = make_float4(-INFINITY, -INFINITY, -INFINITY, -INFINITY);

    if (cnt > 0) {
        int npair = (cnt + 1) >> 1;
        EdgeStage stA;
        stage_load(xkl, emeta, beg + min(half, cnt - 1), stA);
        for (int i = 1; i < npair; ++i) {
            EdgeStage stB;
            stage_load(xkl, emeta, beg + min(2 * i + half, cnt - 1), stB);
            stage_consume(stA, macc);
            stA = stB;
        }
        stage_consume(stA, macc);
    }

    macc.x = fmaxf(macc.x, __shfl_xor_sync(0xffffffffu, macc.x, 16));
    macc.y = fmaxf(macc.y, __shfl_xor_sync(0xffffffffu, macc.y, 16));
    macc.z = fmaxf(macc.z, __shfl_xor_sync(0xffffffffu, macc.z, 16));
    macc.w = fmaxf(macc.w, __shfl_xor_sync(0xffffffffu, macc.w, 16));

    if (lane < 16) {
        size_t o = (size_t)node * C + c4;
        if (!isfinite(macc.x)) macc.x = 0.0f;   // empty node -> 0 (PyG convention)
        if (!isfinite(macc.y)) macc.y = 0.0f;
        if (!isfinite(macc.z)) macc.z = 0.0f;
        if (!isfinite(macc.w)) macc.w = 0.0f;
        float4 r = *(const float4*)&rootout[o];
        macc.x += r.x; macc.y += r.y; macc.z += r.z; macc.w += r.w;
        if (do_relu) {
            macc.x = fmaxf(macc.x, 0.0f);
            macc.y = fmaxf(macc.y, 0.0f);
            macc.z = fmaxf(macc.z, 0.0f);
            macc.w = fmaxf(macc.w, 0.0f);
        }
        *(float4*)&out[o] = macc;
    }
}

// ---------------------------------------------------------------------------
extern "C" void kernel_launch(void* const* d_in, const int* in_sizes, int n_in,
                              void* d_out, int out_size) {
    const float* x      = (const float*)d_in[0];
    const int*   ei     = (const int*)  d_in[1];
    const float* pseudo = (const float*)d_in[2];
    const float* W1     = (const float*)d_in[3];
    const float* root1  = (const float*)d_in[4];
    const float* bias1  = (const float*)d_in[5];
    const float* W2     = (const float*)d_in[6];
    const float* root2  = (const float*)d_in[7];
    const float* bias2  = (const float*)d_in[8];

    const int N = in_sizes[0] / C;
    const int E = in_sizes[1] / 2;
    const int* src = ei;
    const int* dst = ei + E;

    __half* xk;
    float *h, *rootout;
    uint2 *wf1, *wf2, *emeta;
    int *deg, *cur, *off, *offp, *bsum;
    cudaGetSymbolAddress((void**)&xk,      g_xk);
    cudaGetSymbolAddress((void**)&h,       g_h);
    cudaGetSymbolAddress((void**)&rootout, g_rootout);
    cudaGetSymbolAddress((void**)&wf1,     g_wf1);
    cudaGetSymbolAddress((void**)&wf2,     g_wf2);
    cudaGetSymbolAddress((void**)&deg,     g_deg);
    cudaGetSymbolAddress((void**)&cur,     g_cursor);
    cudaGetSymbolAddress((void**)&off,     g_off);
    cudaGetSymbolAddress((void**)&offp,    g_offp);
    cudaGetSymbolAddress((void**)&bsum,    g_bsum);
    cudaGetSymbolAddress((void**)&emeta,   g_emeta);

    // fork/join resources (created once, on the uncaptured correctness call)
    static cudaStream_t s1 = nullptr;
    static cudaEvent_t evFork = nullptr, evSetup = nullptr;
    if (s1 == nullptr) {
        cudaStreamCreateWithFlags(&s1, cudaStreamNonBlocking);
        cudaEventCreateWithFlags(&evFork,  cudaEventDisableTiming);
        cudaEventCreateWithFlags(&evSetup, cudaEventDisableTiming);
    }

    const int NB = (N + SCAN_B - 1) / SCAN_B;
    const int gemmBlocks = (N + 255) / 256;
    const int aggBlocks  = (N + 7) / 8;
    const int eBlocks    = (E + 255) / 256;
    const int wfTotal    = 26 * 4 * 8 * 32;

    // ---- fork: edge bucketing + cvt_w2 on s1; cvt_w1 + gemm1 on stream 0 ----
    cudaEventRecord(evFork, 0);
    cudaStreamWaitEvent(s1, evFork, 0);

    // stream 0: layer-1 weights + GEMM (independent of bucketing)
    cvt_w_kernel<<<(wfTotal + 255) / 256, 256>>>(W1, root1, wf1);
    gemm_xk_kernel<<<gemmBlocks, 256>>>(x, wf1, bias1, xk, rootout, N);

    // s1: edge bucketing chain (dst-only) + layer-2 weights
    zero_kernel<<<(N + 255) / 256, 256, 0, s1>>>(deg, cur, N);
    hist_kernel<<<eBlocks, 256, 0, s1>>>(dst, deg, E);
    scan_local_kernel<<<NB, SCAN_B, 0, s1>>>(deg, offp, bsum, N);
    scan_bsum_kernel<<<1, 64, 0, s1>>>(bsum, NB);
    scan_add_kernel<<<(N + 255) / 256, 256, 0, s1>>>(offp, bsum, off, N);
    scatter_kernel<<<eBlocks, 256, 0, s1>>>(src, dst, pseudo, off, cur, emeta, E);
    cvt_w_kernel<<<(wfTotal + 255) / 256, 256, 0, s1>>>(W2, root2, wf2);
    cudaEventRecord(evSetup, s1);

    // join: aggregation needs emeta + xk
    cudaStreamWaitEvent(0, evSetup, 0);

    // ---- Layer 1: fused aggregation + finalize ----
    agg_fused_kernel<<<aggBlocks, 256>>>(xk, emeta, off, deg, rootout, h, N, 1);

    // ---- Layer 2 ----
    gemm_xk_kernel<<<gemmBlocks, 256>>>(h, wf2, bias2, xk, rootout, N);
    agg_fused_kernel<<<aggBlocks, 256>>>(xk, emeta, off, deg, rootout, (float*)d_out, N, 0);
}